// round 15
// baseline (speedup 1.0000x reference)
#include <cuda_runtime.h>
#include <cuda_bf16.h>

// NuclearLossFunc: loss = sum(x^2) / (B*C), x: (32,64,256,256) fp32
// = 134,217,728 elements = 512 MiB read. Pure HBM-bound reduction.
//
// R15: occupancy-vs-depth test. 296 CTAs x 512 thr = 1024 thr/SM
// (2 CTAs/SM) -> 64 regs/thread available, vs the 32-reg knife-edge at
// 2048 thr/SM that capped the software pipeline at ~2 in-flight float4
// per thread in every prior variant. Hot loop front-batches 4
// independent grid-stride float4 loads per iteration (same outstanding
// bytes/SM as champion, half the warps). Epilogue identical to R6.
// Deterministic: fixed trees, final accumulate in double.

#define NBLOCKS  296            // 148 SMs * 2 CTAs -> one wave @ 1024 thr/SM
#define NTHREADS 512

__device__ float        g_partials[NBLOCKS];
__device__ unsigned int g_count;   // zero-initialized at module load

__global__ __launch_bounds__(NTHREADS) void sqsum_deep_kernel(
    const float4* __restrict__ in, long long n4,
    float* __restrict__ out, float scale)
{
    const int lane = threadIdx.x & 31;
    const int wid  = threadIdx.x >> 5;
    __shared__ float ws[NTHREADS / 32];
    __shared__ bool  s_is_last;

    // ---- hot loop: 4 front-batched independent load streams ----
    float s0 = 0.f, s1 = 0.f, s2 = 0.f, s3 = 0.f;
    float t0 = 0.f, t1 = 0.f, t2 = 0.f, t3 = 0.f;
    long long idx    = (long long)blockIdx.x * blockDim.x + threadIdx.x;
    long long stride = (long long)gridDim.x * blockDim.x;   // 151,552

    long long i = idx;
    for (; i + 3 * stride < n4; i += 4 * stride) {
        float4 a = in[i];
        float4 b = in[i +     stride];
        float4 c = in[i + 2 * stride];
        float4 d = in[i + 3 * stride];
        s0 = fmaf(a.x, a.x, s0);  s1 = fmaf(a.y, a.y, s1);
        s2 = fmaf(a.z, a.z, s2);  s3 = fmaf(a.w, a.w, s3);
        t0 = fmaf(b.x, b.x, t0);  t1 = fmaf(b.y, b.y, t1);
        t2 = fmaf(b.z, b.z, t2);  t3 = fmaf(b.w, b.w, t3);
        s0 = fmaf(c.x, c.x, s0);  s1 = fmaf(c.y, c.y, s1);
        s2 = fmaf(c.z, c.z, s2);  s3 = fmaf(c.w, c.w, s3);
        t0 = fmaf(d.x, d.x, t0);  t1 = fmaf(d.y, d.y, t1);
        t2 = fmaf(d.z, d.z, t2);  t3 = fmaf(d.w, d.w, t3);
    }
    for (; i < n4; i += stride) {           // tail
        float4 a = in[i];
        s0 = fmaf(a.x, a.x, s0);  s1 = fmaf(a.y, a.y, s1);
        s2 = fmaf(a.z, a.z, s2);  s3 = fmaf(a.w, a.w, s3);
    }
    float s = ((s0 + t0) + (s1 + t1)) + ((s2 + t2) + (s3 + t3));

    #pragma unroll
    for (int o = 16; o > 0; o >>= 1)
        s += __shfl_xor_sync(0xffffffffu, s, o);

    if (lane == 0) ws[wid] = s;
    __syncthreads();

    if (wid == 0) {
        s = (lane < NTHREADS / 32) ? ws[lane] : 0.f;
        #pragma unroll
        for (int o = 16; o > 0; o >>= 1)
            s += __shfl_xor_sync(0xffffffffu, s, o);
        if (lane == 0) g_partials[blockIdx.x] = s;   // released by atomic below
    }

    // ---- election: one acq_rel atomic, no fence ----
    if (threadIdx.x == 0) {
        unsigned int ticket;
        asm volatile("atom.add.acq_rel.gpu.u32 %0, [%1], 1;"
                     : "=r"(ticket) : "l"(&g_count) : "memory");
        s_is_last = (ticket == (unsigned int)(gridDim.x - 1));
    }
    __syncthreads();
    if (!s_is_last) return;

    // ---- last block: reduce 296 partials in double (deterministic) ----
    __shared__ double wd[NTHREADS / 32];
    double d = 0.0;
    for (int p = threadIdx.x; p < NBLOCKS; p += NTHREADS)
        d += (double)g_partials[p];

    #pragma unroll
    for (int o = 16; o > 0; o >>= 1)
        d += __shfl_xor_sync(0xffffffffu, d, o);

    if (lane == 0) wd[wid] = d;
    __syncthreads();

    if (wid == 0) {
        d = (lane < NTHREADS / 32) ? wd[lane] : 0.0;
        #pragma unroll
        for (int o = 16; o > 0; o >>= 1)
            d += __shfl_xor_sync(0xffffffffu, d, o);
        if (lane == 0) {
            out[0] = (float)(d * (double)scale);
            g_count = 0;  // reset for graph replay
        }
    }
}

extern "C" void kernel_launch(void* const* d_in, const int* in_sizes, int n_in,
                              void* d_out, int out_size)
{
    const float* x = (const float*)d_in[0];
    long long n = (long long)in_sizes[0];     // 134217728, divisible by 4
    long long n4 = n >> 2;

    // B*C = n / (256*256) = 2048
    float scale = 1.0f / (float)(n / (256LL * 256LL));

    sqsum_deep_kernel<<<NBLOCKS, NTHREADS>>>((const float4*)x, n4,
                                             (float*)d_out, scale);
}

// round 16
// speedup vs baseline: 1.0097x; 1.0097x over previous
#include <cuda_runtime.h>
#include <cuda_bf16.h>

// NuclearLossFunc: loss = sum(x^2) / (B*C), x: (32,64,256,256) fp32
// = 134,217,728 elements = 512 MiB read. Pure HBM-bound reduction.
//
// FINAL (champion, 15-round convergence). 592 CTAs x 512 thr = one
// wave at 2048 thr/SM, exactly 32 regs/thread (full residency).
// Static grid-stride float4 loop: 7.87 TB/s while DRAM-busy; the
// DRAM-active time (~68.2us) is invariant across every mechanism
// tested (2x/4x unroll, 256-bit loads, cache ops, blocked addressing,
// CTA/warp work-stealing with sharded counters, PDL split, TMA
// bulk-copy pipeline, 1024 thr/SM deep-pipeline) -> remaining idle is
// HBM substrate physics, not kernel structure.
// Fused finalize: last-block-done election via one atom.add.acq_rel.gpu
// (release: same-thread partial store; acquire: last block's reads).
// Deterministic: fixed reduction trees; final accumulate in double;
// counter reset for graph replay.

#define NBLOCKS  592            // 148 SMs * 4 CTAs -> exactly one wave
#define NTHREADS 512

__device__ float        g_partials[NBLOCKS];
__device__ unsigned int g_count;   // zero-initialized at module load

__global__ __launch_bounds__(NTHREADS) void sqsum_fused_kernel(
    const float4* __restrict__ in, long long n4,
    float* __restrict__ out, float scale)
{
    const int lane = threadIdx.x & 31;
    const int wid  = threadIdx.x >> 5;
    __shared__ float ws[NTHREADS / 32];
    __shared__ bool  s_is_last;

    // ---- hot loop: measured best; do not touch ----
    float s0 = 0.f, s1 = 0.f, s2 = 0.f, s3 = 0.f;
    long long idx    = (long long)blockIdx.x * blockDim.x + threadIdx.x;
    long long stride = (long long)gridDim.x * blockDim.x;

    for (long long i = idx; i < n4; i += stride) {
        float4 v = in[i];
        s0 = fmaf(v.x, v.x, s0);
        s1 = fmaf(v.y, v.y, s1);
        s2 = fmaf(v.z, v.z, s2);
        s3 = fmaf(v.w, v.w, s3);
    }
    float s = (s0 + s1) + (s2 + s3);

    #pragma unroll
    for (int o = 16; o > 0; o >>= 1)
        s += __shfl_xor_sync(0xffffffffu, s, o);

    if (lane == 0) ws[wid] = s;
    __syncthreads();

    if (wid == 0) {
        s = (lane < NTHREADS / 32) ? ws[lane] : 0.f;
        #pragma unroll
        for (int o = 16; o > 0; o >>= 1)
            s += __shfl_xor_sync(0xffffffffu, s, o);
        if (lane == 0) g_partials[blockIdx.x] = s;   // released by atomic below
    }

    // ---- last-block election: one acq_rel atomic, no fence ----
    if (threadIdx.x == 0) {
        unsigned int ticket;
        asm volatile("atom.add.acq_rel.gpu.u32 %0, [%1], 1;"
                     : "=r"(ticket) : "l"(&g_count) : "memory");
        s_is_last = (ticket == (unsigned int)(gridDim.x - 1));
    }
    __syncthreads();
    if (!s_is_last) return;

    // ---- last block: reduce 592 partials in double (deterministic) ----
    __shared__ double wd[NTHREADS / 32];
    double d = 0.0;
    for (int p = threadIdx.x; p < NBLOCKS; p += NTHREADS)
        d += (double)g_partials[p];

    #pragma unroll
    for (int o = 16; o > 0; o >>= 1)
        d += __shfl_xor_sync(0xffffffffu, d, o);

    if (lane == 0) wd[wid] = d;
    __syncthreads();

    if (wid == 0) {
        d = (lane < NTHREADS / 32) ? wd[lane] : 0.0;
        #pragma unroll
        for (int o = 16; o > 0; o >>= 1)
            d += __shfl_xor_sync(0xffffffffu, d, o);
        if (lane == 0) {
            out[0] = (float)(d * (double)scale);
            g_count = 0;  // reset for graph replay
        }
    }
}

extern "C" void kernel_launch(void* const* d_in, const int* in_sizes, int n_in,
                              void* d_out, int out_size)
{
    const float* x = (const float*)d_in[0];
    long long n = (long long)in_sizes[0];     // 134217728, divisible by 4
    long long n4 = n >> 2;

    // B*C = n / (256*256) = 2048
    float scale = 1.0f / (float)(n / (256LL * 256LL));

    sqsum_fused_kernel<<<NBLOCKS, NTHREADS>>>((const float4*)x, n4,
                                              (float*)d_out, scale);
}